// round 13
// baseline (speedup 1.0000x reference)
#include <cuda_runtime.h>
#include <cuda_fp16.h>
#include <cstdint>

#define N_NODES 100000
#define N_EDGES 1600000
#define D 128
#define L_LAYERS 3

#define KPADH 144           // fp16 units per half-weight row (128 data + 16 pad; 72 words ≡ 8 mod 32)
#define APAD 48             // fp16 units per A-tile row (32 data + 16 pad; 24 words, conflict-free)
#define GEMM_TILES ((N_NODES + 127) / 128)   // 782
#define SELF_GRID 148       // 1 CTA/SM: leaves room for agg co-residency
#define NEIGH_GRID 296      // 2 CTA/SM

// ---------------- scratch (no allocations allowed) ----------------
__device__ int    g_deg[N_NODES];
__device__ float  g_invdeg[N_NODES];
__device__ int    g_off[N_NODES + 1];
__device__ int    g_cursor[N_NODES];
__device__ int    g_csr[N_EDGES];
__device__ __align__(16) __half g_xf16[(size_t)N_NODES * D];
__device__ __align__(16) __half g_hf16a[(size_t)N_NODES * D];
__device__ __align__(16) __half g_hf16b[(size_t)N_NODES * D];
__device__ __align__(16) __half g_hn16[(size_t)N_NODES * D];
__device__ __align__(16) float  g_acc[(size_t)N_NODES * D];
// fp16 weights: [layer][self|neigh][n=128][KPADH], transposed + permuted-K
__device__ __align__(16) __half g_wt16[6 * 128 * KPADH];

// ---------------- CSR build ----------------
__global__ void zero_deg_kernel() {
    int i = blockIdx.x * blockDim.x + threadIdx.x;
    if (i < N_NODES) g_deg[i] = 0;
}

__global__ void count_deg_kernel(const int* __restrict__ dst) {
    int e = blockIdx.x * blockDim.x + threadIdx.x;
    if (e < N_EDGES) atomicAdd(&g_deg[dst[e]], 1);
}

__global__ void scan_offsets_kernel() {
    __shared__ int warp_sums[32];
    __shared__ int carry_sh;
    int t = threadIdx.x, lane = t & 31, w = t >> 5;
    if (t == 0) carry_sh = 0;
    __syncthreads();
    for (int base = 0; base < N_NODES; base += 4096) {
        int i4 = base + t * 4;
        int4 v = make_int4(0, 0, 0, 0);
        if (i4 < N_NODES) v = *(const int4*)&g_deg[i4];
        int s0 = v.x, s1 = s0 + v.y, s2 = s1 + v.z, s3 = s2 + v.w;
        int incl = s3;
        #pragma unroll
        for (int off = 1; off < 32; off <<= 1) {
            int x = __shfl_up_sync(0xffffffffu, incl, off);
            if (lane >= off) incl += x;
        }
        if (lane == 31) warp_sums[w] = incl;
        __syncthreads();
        if (w == 0) {
            int s = warp_sums[lane];
            #pragma unroll
            for (int off = 1; off < 32; off <<= 1) {
                int x = __shfl_up_sync(0xffffffffu, s, off);
                if (lane >= off) s += x;
            }
            warp_sums[lane] = s;
        }
        __syncthreads();
        int carry = carry_sh;
        int woff = (w > 0) ? warp_sums[w - 1] : 0;
        int excl = carry + woff + incl - s3;
        if (i4 < N_NODES) {
            *(int4*)&g_off[i4] =
                make_int4(excl, excl + s0, excl + s1, excl + s2);
            *(float4*)&g_invdeg[i4] = make_float4(
                1.0f / (float)max(v.x, 1), 1.0f / (float)max(v.y, 1),
                1.0f / (float)max(v.z, 1), 1.0f / (float)max(v.w, 1));
            *(int4*)&g_cursor[i4] = make_int4(0, 0, 0, 0);
        }
        __syncthreads();
        if (t == 1023) carry_sh = carry + woff + incl;
        __syncthreads();
    }
    if (t == 0) g_off[N_NODES] = carry_sh;
}

__global__ void fill_csr_kernel(const int* __restrict__ src,
                                const int* __restrict__ dst) {
    int e = blockIdx.x * blockDim.x + threadIdx.x;
    if (e < N_EDGES) {
        int d = dst[e];
        int p = atomicAdd(&g_cursor[d], 1);
        g_csr[g_off[d] + p] = src[e];
    }
}

// ---------------- x -> fp16 copy (once) ----------------
__global__ void convert_x_kernel(const float* __restrict__ x) {
    int i = blockIdx.x * blockDim.x + threadIdx.x;
    if (i < N_NODES * D / 4) {
        float4 v = ((const float4*)x)[i];
        __half2* o = (__half2*)g_xf16;
        o[i * 2]     = __floats2half2_rn(v.x, v.y);
        o[i * 2 + 1] = __floats2half2_rn(v.z, v.w);
    }
}

// ---------------- weight prep: fp16, transposed + permuted-K, all layers -----
// index: [l][which (0=self,1=neigh)][n][k 0..127]
__global__ void prep_w_kernel(const float* __restrict__ Ws,
                              const float* __restrict__ Wn) {
    int idx = blockIdx.x * blockDim.x + threadIdx.x;
    if (idx >= 6 * 128 * 128) return;
    int slab = idx >> 14;              // l*2 + which
    int rem = idx & 16383;
    int n = rem >> 7;
    int k = rem & 127;
    int l = slab >> 1, which = slab & 1;
    const float* W = which ? Wn : Ws;
    float w = __ldg(&W[(size_t)l * D * D + k * 128 + n]);
    int group = k >> 4, li = k & 15;
    int p = ((li & 7) >> 1) * 4 + (li & 1) + ((li >> 3) << 1);
    g_wt16[(slab * 128 + n) * KPADH + group * 16 + p] = __float2half_rn(w);
}

// ---------------- aggregation: one warp per node, fp16 gather, unroll 8 ------
__device__ __forceinline__ void acc_h4(float4& a, uint2 r) {
    __half2 p0 = *reinterpret_cast<__half2*>(&r.x);
    __half2 p1 = *reinterpret_cast<__half2*>(&r.y);
    float2 f0 = __half22float2(p0);
    float2 f1 = __half22float2(p1);
    a.x += f0.x; a.y += f0.y; a.z += f1.x; a.w += f1.y;
}

__global__ void __launch_bounds__(256) aggregate_f16_kernel(
    const __half* __restrict__ hin16)
{
    int gw = (blockIdx.x * blockDim.x + threadIdx.x) >> 5;
    int lane = threadIdx.x & 31;
    if (gw >= N_NODES) return;
    int s = g_off[gw], e = g_off[gw + 1];
    const uint2* H = (const uint2*)hin16;
    float4 a[8];
    #pragma unroll
    for (int i = 0; i < 8; i++) a[i] = make_float4(0.f, 0.f, 0.f, 0.f);
    int j = s;
    for (; j + 8 <= e; j += 8) {
        int u[8];
        #pragma unroll
        for (int i = 0; i < 8; i++) u[i] = __ldg(&g_csr[j + i]);
        uint2 r[8];
        #pragma unroll
        for (int i = 0; i < 8; i++) r[i] = __ldg(&H[(size_t)u[i] * 32 + lane]);
        #pragma unroll
        for (int i = 0; i < 8; i++) acc_h4(a[i], r[i]);
    }
    for (; j + 2 <= e; j += 2) {
        int u0 = __ldg(&g_csr[j]);
        int u1 = __ldg(&g_csr[j + 1]);
        uint2 r0 = __ldg(&H[(size_t)u0 * 32 + lane]);
        uint2 r1 = __ldg(&H[(size_t)u1 * 32 + lane]);
        acc_h4(a[0], r0); acc_h4(a[1], r1);
    }
    if (j < e) {
        int u = __ldg(&g_csr[j]);
        uint2 r = __ldg(&H[(size_t)u * 32 + lane]);
        acc_h4(a[0], r);
    }
    #pragma unroll
    for (int i = 4; i < 8; i++) {
        a[i - 4].x += a[i].x; a[i - 4].y += a[i].y;
        a[i - 4].z += a[i].z; a[i - 4].w += a[i].w;
    }
    float inv = g_invdeg[gw];
    __half2 o0 = __floats2half2_rn((a[0].x + a[1].x + a[2].x + a[3].x) * inv,
                                   (a[0].y + a[1].y + a[2].y + a[3].y) * inv);
    __half2 o1 = __floats2half2_rn((a[0].z + a[1].z + a[2].z + a[3].z) * inv,
                                   (a[0].w + a[1].w + a[2].w + a[3].w) * inv);
    uint2 o;
    o.x = *reinterpret_cast<uint32_t*>(&o0);
    o.y = *reinterpret_cast<uint32_t*>(&o1);
    ((uint2*)g_hn16)[(size_t)gw * 32 + lane] = o;
}

// ---------------- persistent half-K fp16 GEMM (8 warps) ----------------------
// mode self  (accOut != 0): accOut = A*W          (fp32, no bias/relu)
// mode neigh (accOut == 0): r = relu(A*W + accIn + bias) -> out32/out16
#define ABUF (128 * APAD)
#define GEMM_SMEM_BYTES ((128 * KPADH + 2 * ABUF) * 2)   // 61440 B

__device__ __forceinline__ void mma_f16(float c[4], uint32_t a0, uint32_t a1,
                                        uint32_t a2, uint32_t a3,
                                        uint32_t b0, uint32_t b1) {
    asm volatile(
        "mma.sync.aligned.m16n8k16.row.col.f32.f16.f16.f32 "
        "{%0,%1,%2,%3}, {%4,%5,%6,%7}, {%8,%9}, {%0,%1,%2,%3};"
        : "+f"(c[0]), "+f"(c[1]), "+f"(c[2]), "+f"(c[3])
        : "r"(a0), "r"(a1), "r"(a2), "r"(a3), "r"(b0), "r"(b1));
}

__global__ void __launch_bounds__(256, 2) sage_gemm_half_kernel(
    const __half* __restrict__ A16, const __half* __restrict__ wt,
    const float* __restrict__ bias, const float* __restrict__ accIn,
    float* __restrict__ accOut, float* __restrict__ out32,
    __half* __restrict__ out16)
{
    extern __shared__ __align__(16) __half smem[];
    __half* sW = smem;                    // [128][KPADH]
    __half* sAbuf = sW + 128 * KPADH;     // 2 x [128][APAD]

    int tid = threadIdx.x;
    int lane = tid & 31, warp = tid >> 5;
    int warpM = warp & 3, warpN = warp >> 2;          // 4 x 2 warp grid
    int g = lane >> 2, tig = lane & 3;

    // stage fp16 weights once per CTA (2304 uint4)
    {
        const uint4* s0 = (const uint4*)wt;
        uint4* d0 = (uint4*)sW;
        for (int i = tid; i < (128 * KPADH) / 8; i += 256)
            d0[i] = s0[i];
    }

    float bx[8], by[8];
    #pragma unroll
    for (int nf = 0; nf < 8; nf++) {
        int col = warpN * 64 + nf * 8 + tig * 2;
        bx[nf] = __ldg(&bias[col]);
        by[nf] = __ldg(&bias[col + 1]);
    }

    const int ptab[4] = {0, 8, 2, 10};

    for (int tile = blockIdx.x; tile < GEMM_TILES; tile += gridDim.x) {
        int m0 = tile * 128;

        float acc[2][8][4];
        #pragma unroll
        for (int mf = 0; mf < 2; mf++)
            #pragma unroll
            for (int nf = 0; nf < 8; nf++)
                #pragma unroll
                for (int r = 0; r < 4; r++) acc[mf][nf][r] = 0.f;

        // preload chunk 0 (cols 0..31)
        uint2 pref[4];
        #pragma unroll
        for (int i = 0; i < 4; i++) {
            int idx = tid + 256 * i;
            int r = idx >> 3, c4 = idx & 7;
            int m = m0 + r;
            pref[i] = make_uint2(0u, 0u);
            if (m < N_NODES)
                pref[i] = __ldg((const uint2*)(A16 + (size_t)m * D + c4 * 4));
        }

        #pragma unroll 1
        for (int kc = 0; kc < 4; kc++) {
            __half* sA = sAbuf + (kc & 1) * ABUF;

            #pragma unroll
            for (int i = 0; i < 4; i++) {
                int idx = tid + 256 * i;
                int r = idx >> 3, c4 = idx & 7;
                int group = c4 >> 2;
                int p0 = ptab[c4 & 3];
                int base = r * APAD + group * 16;
                uint32_t* A32 = (uint32_t*)sA;
                A32[(base + p0) >> 1]     = pref[i].x;
                A32[(base + p0 + 4) >> 1] = pref[i].y;
            }
            __syncthreads();   // first iteration also covers W staging

            if (kc < 3) {
                int koff = (kc + 1) * 32;
                #pragma unroll
                for (int i = 0; i < 4; i++) {
                    int idx = tid + 256 * i;
                    int r = idx >> 3, c4 = idx & 7;
                    int m = m0 + r;
                    pref[i] = make_uint2(0u, 0u);
                    if (m < N_NODES)
                        pref[i] = __ldg((const uint2*)(A16 + (size_t)m * D +
                                                       koff + c4 * 4));
                }
            }

            #pragma unroll
            for (int ks = 0; ks < 2; ks++) {
                int ka = ks * 16;
                int kw = kc * 32 + ks * 16;
                uint32_t A[2][4];
                #pragma unroll
                for (int mf = 0; mf < 2; mf++) {
                    int r0 = warpM * 32 + mf * 16;
                    uint2 t0 = *(const uint2*)&sA[(r0 + g) * APAD + ka + tig * 4];
                    uint2 t1 = *(const uint2*)&sA[(r0 + g + 8) * APAD + ka + tig * 4];
                    A[mf][0] = t0.x; A[mf][1] = t1.x; A[mf][2] = t0.y; A[mf][3] = t1.y;
                }
                #pragma unroll
                for (int nf = 0; nf < 8; nf++) {
                    int nr = warpN * 64 + nf * 8 + g;
                    uint2 b = *(const uint2*)&sW[nr * KPADH + kw + tig * 4];
                    #pragma unroll
                    for (int mf = 0; mf < 2; mf++)
                        mma_f16(acc[mf][nf], A[mf][0], A[mf][1], A[mf][2], A[mf][3],
                                b.x, b.y);
                }
            }
        }

        // epilogue
        #pragma unroll
        for (int mf = 0; mf < 2; mf++) {
            #pragma unroll
            for (int nf = 0; nf < 8; nf++) {
                int row0 = m0 + warpM * 32 + mf * 16 + g;
                int col = warpN * 64 + nf * 8 + tig * 2;
                if (accOut) {
                    // self pass: raw fp32 partial
                    if (row0 < N_NODES)
                        *(float2*)&accOut[(size_t)row0 * D + col] =
                            make_float2(acc[mf][nf][0], acc[mf][nf][1]);
                    if (row0 + 8 < N_NODES)
                        *(float2*)&accOut[(size_t)(row0 + 8) * D + col] =
                            make_float2(acc[mf][nf][2], acc[mf][nf][3]);
                } else {
                    // neigh pass: + self partial + bias, relu, store
                    if (row0 < N_NODES) {
                        float2 p = *(const float2*)&accIn[(size_t)row0 * D + col];
                        float r0 = acc[mf][nf][0] + p.x + bx[nf]; r0 = r0 > 0.f ? r0 : 0.f;
                        float r1 = acc[mf][nf][1] + p.y + by[nf]; r1 = r1 > 0.f ? r1 : 0.f;
                        if (out32) *(float2*)&out32[(size_t)row0 * D + col] =
                            make_float2(r0, r1);
                        if (out16) *(__half2*)&out16[(size_t)row0 * D + col] =
                            __floats2half2_rn(r0, r1);
                    }
                    if (row0 + 8 < N_NODES) {
                        float2 p = *(const float2*)&accIn[(size_t)(row0 + 8) * D + col];
                        float r2 = acc[mf][nf][2] + p.x + bx[nf]; r2 = r2 > 0.f ? r2 : 0.f;
                        float r3 = acc[mf][nf][3] + p.y + by[nf]; r3 = r3 > 0.f ? r3 : 0.f;
                        if (out32) *(float2*)&out32[(size_t)(row0 + 8) * D + col] =
                            make_float2(r2, r3);
                        if (out16) *(__half2*)&out16[(size_t)(row0 + 8) * D + col] =
                            __floats2half2_rn(r2, r3);
                    }
                }
            }
        }
        __syncthreads();   // A buffers reused next tile
    }
}

// ---------------- launch ----------------
extern "C" void kernel_launch(void* const* d_in, const int* in_sizes, int n_in,
                              void* d_out, int out_size)
{
    const float* x       = (const float*)d_in[0];
    const float* W_self  = (const float*)d_in[1];
    const float* W_neigh = (const float*)d_in[2];
    const float* bias    = (const float*)d_in[3];
    const int*   src     = (const int*)d_in[4];
    const int*   dst     = (const int*)d_in[5];
    float* out = (float*)d_out;

    void *px16, *pa16, *pb16, *pn16, *pw, *pacc;
    cudaGetSymbolAddress(&px16, g_xf16);
    cudaGetSymbolAddress(&pa16, g_hf16a);
    cudaGetSymbolAddress(&pb16, g_hf16b);
    cudaGetSymbolAddress(&pn16, g_hn16);
    cudaGetSymbolAddress(&pw, g_wt16);
    cudaGetSymbolAddress(&pacc, g_acc);
    __half* x16 = (__half*)px16;
    __half* a16 = (__half*)pa16;
    __half* b16 = (__half*)pb16;
    __half* hn16 = (__half*)pn16;
    const __half* wt16 = (const __half*)pw;
    float* accp = (float*)pacc;

    static cudaStream_t s2 = nullptr;
    static cudaEvent_t evFork, evS0, evS1, evS2, evG0, evG1, evG2;
    if (s2 == nullptr) {
        cudaStreamCreateWithFlags(&s2, cudaStreamNonBlocking);
        cudaEventCreateWithFlags(&evFork, cudaEventDisableTiming);
        cudaEventCreateWithFlags(&evS0, cudaEventDisableTiming);
        cudaEventCreateWithFlags(&evS1, cudaEventDisableTiming);
        cudaEventCreateWithFlags(&evS2, cudaEventDisableTiming);
        cudaEventCreateWithFlags(&evG0, cudaEventDisableTiming);
        cudaEventCreateWithFlags(&evG1, cudaEventDisableTiming);
        cudaEventCreateWithFlags(&evG2, cudaEventDisableTiming);
        cudaFuncSetAttribute(sage_gemm_half_kernel,
                             cudaFuncAttributeMaxDynamicSharedMemorySize,
                             GEMM_SMEM_BYTES);
    }
    cudaEvent_t evS[3] = {evS0, evS1, evS2};
    cudaEvent_t evG[3] = {evG0, evG1, evG2};

    const size_t WSLAB = (size_t)128 * KPADH;

    // fork: s2 converts x, preps all weights, then runs gemm_self(0) — all of
    // which overlap the CSR build on the main stream.
    cudaEventRecord(evFork, 0);
    cudaStreamWaitEvent(s2, evFork, 0);
    convert_x_kernel<<<(N_NODES * D / 4 + 255) / 256, 256, 0, s2>>>(x);
    prep_w_kernel<<<(6 * 128 * 128 + 255) / 256, 256, 0, s2>>>(W_self, W_neigh);
    sage_gemm_half_kernel<<<SELF_GRID, 256, GEMM_SMEM_BYTES, s2>>>(
        x16, wt16 + 0 * WSLAB, bias, nullptr, accp, nullptr, nullptr);
    cudaEventRecord(evS[0], s2);

    // main: CSR build
    zero_deg_kernel<<<(N_NODES + 255) / 256, 256>>>();
    count_deg_kernel<<<(N_EDGES + 255) / 256, 256>>>(dst);
    scan_offsets_kernel<<<1, 1024>>>();
    fill_csr_kernel<<<(N_EDGES + 255) / 256, 256>>>(src, dst);

    const __half* hin16 = x16;
    __half* houts16[3] = {a16, b16, nullptr};
    float* houts32[3] = {nullptr, nullptr, out};
    for (int l = 0; l < L_LAYERS; l++) {
        // agg(l) on main, concurrent with gemm_self(l) on s2
        aggregate_f16_kernel<<<(N_NODES + 7) / 8, 256>>>(hin16);
        cudaStreamWaitEvent(0, evS[l], 0);
        sage_gemm_half_kernel<<<NEIGH_GRID, 256, GEMM_SMEM_BYTES>>>(
            hn16, wt16 + (size_t)(2 * l + 1) * WSLAB, bias + (size_t)l * D,
            accp, nullptr, houts32[l], houts16[l]);
        cudaEventRecord(evG[l], 0);
        if (l < L_LAYERS - 1) {
            // next layer's self pass on s2 (needs h(l); overlaps agg(l+1))
            cudaStreamWaitEvent(s2, evG[l], 0);
            sage_gemm_half_kernel<<<SELF_GRID, 256, GEMM_SMEM_BYTES, s2>>>(
                houts16[l], wt16 + (size_t)(2 * (l + 1)) * WSLAB,
                bias, nullptr, accp, nullptr, nullptr);
            cudaEventRecord(evS[l + 1], s2);
        }
        hin16 = houts16[l];
    }
    // join s2 before capture ends
    cudaStreamWaitEvent(0, evS[L_LAYERS - 1], 0);
}

// round 14
// speedup vs baseline: 1.1427x; 1.1427x over previous
#include <cuda_runtime.h>
#include <cuda_fp16.h>
#include <cstdint>

#define N_NODES 100000
#define N_EDGES 1600000
#define D 128
#define L_LAYERS 3

#define KPAD 272            // fp16/row: 136 words ≡ 8 (mod 32) -> conflict-free B LDS.64
#define APAD 48             // fp16/row: 24 words -> conflict-free A LDS.64
#define GEMM_TILES ((N_NODES + 127) / 128)   // 782
#define GEMM_GRID 296       // 2 CTAs per SM

// ---------------- scratch (no allocations allowed) ----------------
__device__ int    g_deg[N_NODES];
__device__ float  g_invdeg[N_NODES];
__device__ int    g_off[N_NODES + 1];
__device__ int    g_cursor[N_NODES];
__device__ int    g_csr[N_EDGES];
__device__ __align__(16) __half g_xf16[(size_t)N_NODES * D];
__device__ __align__(16) __half g_hf16a[(size_t)N_NODES * D];
__device__ __align__(16) __half g_hf16b[(size_t)N_NODES * D];
__device__ __align__(16) __half g_hn16[(size_t)N_NODES * D];
// fp16 weights, all 3 layers, transposed + permuted-K layout [l][n=128][KPAD]
__device__ __align__(16) __half g_wt16[3 * 128 * KPAD];

// ---------------- CSR build ----------------
__global__ void zero_deg_kernel() {
    int i = blockIdx.x * blockDim.x + threadIdx.x;
    if (i < N_NODES) g_deg[i] = 0;
}

__global__ void count_deg_kernel(const int* __restrict__ dst) {
    int e = blockIdx.x * blockDim.x + threadIdx.x;
    if (e < N_EDGES) atomicAdd(&g_deg[dst[e]], 1);
}

__global__ void scan_offsets_kernel() {
    __shared__ int warp_sums[32];
    __shared__ int carry_sh;
    int t = threadIdx.x, lane = t & 31, w = t >> 5;
    if (t == 0) carry_sh = 0;
    __syncthreads();
    for (int base = 0; base < N_NODES; base += 4096) {
        int i4 = base + t * 4;
        int4 v = make_int4(0, 0, 0, 0);
        if (i4 < N_NODES) v = *(const int4*)&g_deg[i4];
        int s0 = v.x, s1 = s0 + v.y, s2 = s1 + v.z, s3 = s2 + v.w;
        int incl = s3;
        #pragma unroll
        for (int off = 1; off < 32; off <<= 1) {
            int x = __shfl_up_sync(0xffffffffu, incl, off);
            if (lane >= off) incl += x;
        }
        if (lane == 31) warp_sums[w] = incl;
        __syncthreads();
        if (w == 0) {
            int s = warp_sums[lane];
            #pragma unroll
            for (int off = 1; off < 32; off <<= 1) {
                int x = __shfl_up_sync(0xffffffffu, s, off);
                if (lane >= off) s += x;
            }
            warp_sums[lane] = s;
        }
        __syncthreads();
        int carry = carry_sh;
        int woff = (w > 0) ? warp_sums[w - 1] : 0;
        int excl = carry + woff + incl - s3;
        if (i4 < N_NODES) {
            *(int4*)&g_off[i4] =
                make_int4(excl, excl + s0, excl + s1, excl + s2);
            *(float4*)&g_invdeg[i4] = make_float4(
                1.0f / (float)max(v.x, 1), 1.0f / (float)max(v.y, 1),
                1.0f / (float)max(v.z, 1), 1.0f / (float)max(v.w, 1));
            *(int4*)&g_cursor[i4] = make_int4(0, 0, 0, 0);
        }
        __syncthreads();
        if (t == 1023) carry_sh = carry + woff + incl;
        __syncthreads();
    }
    if (t == 0) g_off[N_NODES] = carry_sh;
}

__global__ void fill_csr_kernel(const int* __restrict__ src,
                                const int* __restrict__ dst) {
    int e = blockIdx.x * blockDim.x + threadIdx.x;
    if (e < N_EDGES) {
        int d = dst[e];
        int p = atomicAdd(&g_cursor[d], 1);
        g_csr[g_off[d] + p] = src[e];
    }
}

// ---------------- x -> fp16 copy (once) ----------------
__global__ void convert_x_kernel(const float* __restrict__ x) {
    int i = blockIdx.x * blockDim.x + threadIdx.x;
    if (i < N_NODES * D / 4) {
        float4 v = ((const float4*)x)[i];
        __half2* o = (__half2*)g_xf16;
        o[i * 2]     = __floats2half2_rn(v.x, v.y);
        o[i * 2 + 1] = __floats2half2_rn(v.z, v.w);
    }
}

// ---------------- weight prep: fp16, transposed + permuted-K, all layers -----
__global__ void prep_w_kernel(const float* __restrict__ Ws,
                              const float* __restrict__ Wn) {
    int idx = blockIdx.x * blockDim.x + threadIdx.x;
    if (idx >= 3 * 128 * 256) return;
    int l = idx / (128 * 256);
    int rem = idx - l * 128 * 256;
    int n = rem >> 8;
    int k = rem & 255;
    float w = (k < 128) ? __ldg(&Ws[(size_t)l * D * D + k * 128 + n])
                        : __ldg(&Wn[(size_t)l * D * D + (k - 128) * 128 + n]);
    int group = k >> 4, li = k & 15;
    int p = ((li & 7) >> 1) * 4 + (li & 1) + ((li >> 3) << 1);
    g_wt16[l * 128 * KPAD + n * KPAD + group * 16 + p] = __float2half_rn(w);
}

// ---------------- aggregation: one warp per node, fp16 gather, unroll 8 ------
__device__ __forceinline__ void acc_h4(float4& a, uint2 r) {
    __half2 p0 = *reinterpret_cast<__half2*>(&r.x);
    __half2 p1 = *reinterpret_cast<__half2*>(&r.y);
    float2 f0 = __half22float2(p0);
    float2 f1 = __half22float2(p1);
    a.x += f0.x; a.y += f0.y; a.z += f1.x; a.w += f1.y;
}

__global__ void __launch_bounds__(256) aggregate_f16_kernel(
    const __half* __restrict__ hin16)
{
    int gw = (blockIdx.x * blockDim.x + threadIdx.x) >> 5;
    int lane = threadIdx.x & 31;
    if (gw >= N_NODES) return;
    int s = g_off[gw], e = g_off[gw + 1];
    const uint2* H = (const uint2*)hin16;
    float4 a[8];
    #pragma unroll
    for (int i = 0; i < 8; i++) a[i] = make_float4(0.f, 0.f, 0.f, 0.f);
    int j = s;
    for (; j + 8 <= e; j += 8) {
        int u[8];
        #pragma unroll
        for (int i = 0; i < 8; i++) u[i] = __ldg(&g_csr[j + i]);
        uint2 r[8];
        #pragma unroll
        for (int i = 0; i < 8; i++) r[i] = __ldg(&H[(size_t)u[i] * 32 + lane]);
        #pragma unroll
        for (int i = 0; i < 8; i++) acc_h4(a[i], r[i]);
    }
    for (; j + 2 <= e; j += 2) {
        int u0 = __ldg(&g_csr[j]);
        int u1 = __ldg(&g_csr[j + 1]);
        uint2 r0 = __ldg(&H[(size_t)u0 * 32 + lane]);
        uint2 r1 = __ldg(&H[(size_t)u1 * 32 + lane]);
        acc_h4(a[0], r0); acc_h4(a[1], r1);
    }
    if (j < e) {
        int u = __ldg(&g_csr[j]);
        uint2 r = __ldg(&H[(size_t)u * 32 + lane]);
        acc_h4(a[0], r);
    }
    #pragma unroll
    for (int i = 4; i < 8; i++) {
        a[i - 4].x += a[i].x; a[i - 4].y += a[i].y;
        a[i - 4].z += a[i].z; a[i - 4].w += a[i].w;
    }
    float inv = g_invdeg[gw];
    __half2 o0 = __floats2half2_rn((a[0].x + a[1].x + a[2].x + a[3].x) * inv,
                                   (a[0].y + a[1].y + a[2].y + a[3].y) * inv);
    __half2 o1 = __floats2half2_rn((a[0].z + a[1].z + a[2].z + a[3].z) * inv,
                                   (a[0].w + a[1].w + a[2].w + a[3].w) * inv);
    uint2 o;
    o.x = *reinterpret_cast<uint32_t*>(&o0);
    o.y = *reinterpret_cast<uint32_t*>(&o1);
    ((uint2*)g_hn16)[(size_t)gw * 32 + lane] = o;
}

// ---------------- persistent single-product fp16 GEMM (8 warps, 2 CTA/SM) ----
//   C = A * W  (fp32 accum, m16n8k16 f16 mma.sync), A = [h16 | hn16]
#define ABUF (128 * APAD)                          // fp16 units per buffer
#define GEMM_SMEM_BYTES ((128 * KPAD + 2 * ABUF) * 2)   // 94208 B

__device__ __forceinline__ void mma_f16(float c[4], uint32_t a0, uint32_t a1,
                                        uint32_t a2, uint32_t a3,
                                        uint32_t b0, uint32_t b1) {
    asm volatile(
        "mma.sync.aligned.m16n8k16.row.col.f32.f16.f16.f32 "
        "{%0,%1,%2,%3}, {%4,%5,%6,%7}, {%8,%9}, {%0,%1,%2,%3};"
        : "+f"(c[0]), "+f"(c[1]), "+f"(c[2]), "+f"(c[3])
        : "r"(a0), "r"(a1), "r"(a2), "r"(a3), "r"(b0), "r"(b1));
}

__global__ void __launch_bounds__(256, 2) sage_gemm_kernel(
    const __half* __restrict__ h16, const __half* __restrict__ hn16,
    const __half* __restrict__ wt16, const float* __restrict__ bias,
    float* __restrict__ out32, __half* __restrict__ out16)
{
    extern __shared__ __align__(16) __half smem[];
    __half* sW = smem;                    // [128][KPAD]
    __half* sAbuf = sW + 128 * KPAD;      // 2 x [128][APAD]

    int tid = threadIdx.x;
    int lane = tid & 31, warp = tid >> 5;
    int warpM = warp & 3, warpN = warp >> 2;          // 4 x 2 warp grid
    int g = lane >> 2, tig = lane & 3;

    // stage fp16 weights once per CTA (4352 uint4)
    {
        const uint4* s0 = (const uint4*)wt16;
        uint4* d0 = (uint4*)sW;
        for (int i = tid; i < (128 * KPAD) / 8; i += 256)
            d0[i] = s0[i];
    }

    float bx[8], by[8];
    #pragma unroll
    for (int nf = 0; nf < 8; nf++) {
        int col = warpN * 64 + nf * 8 + tig * 2;
        bx[nf] = __ldg(&bias[col]);
        by[nf] = __ldg(&bias[col + 1]);
    }

    const int ptab[4] = {0, 8, 2, 10};

    for (int tile = blockIdx.x; tile < GEMM_TILES; tile += gridDim.x) {
        int m0 = tile * 128;

        float acc[2][8][4];
        #pragma unroll
        for (int mf = 0; mf < 2; mf++)
            #pragma unroll
            for (int nf = 0; nf < 8; nf++)
                #pragma unroll
                for (int r = 0; r < 4; r++) acc[mf][nf][r] = 0.f;

        // preload chunk 0 (self, cols 0..31): 1024 uint2, 4 per thread
        uint2 pref[4];
        #pragma unroll
        for (int i = 0; i < 4; i++) {
            int idx = tid + 256 * i;
            int r = idx >> 3, c4 = idx & 7;
            int m = m0 + r;
            pref[i] = make_uint2(0u, 0u);
            if (m < N_NODES)
                pref[i] = __ldg((const uint2*)(h16 + (size_t)m * D + c4 * 4));
        }

        #pragma unroll 1
        for (int kc = 0; kc < 8; kc++) {
            __half* sA = sAbuf + (kc & 1) * ABUF;

            // store prefetched fp16 into permuted-K smem
            #pragma unroll
            for (int i = 0; i < 4; i++) {
                int idx = tid + 256 * i;
                int r = idx >> 3, c4 = idx & 7;
                int group = c4 >> 2;
                int p0 = ptab[c4 & 3];
                int base = r * APAD + group * 16;
                uint32_t* A32 = (uint32_t*)sA;
                A32[(base + p0) >> 1]     = pref[i].x;
                A32[(base + p0 + 4) >> 1] = pref[i].y;
            }
            __syncthreads();   // first iteration also covers W staging

            if (kc < 7) {
                int nkc = kc + 1;
                const __half* srcp = (nkc < 4) ? h16 : hn16;
                int koff = (nkc & 3) * 32;
                #pragma unroll
                for (int i = 0; i < 4; i++) {
                    int idx = tid + 256 * i;
                    int r = idx >> 3, c4 = idx & 7;
                    int m = m0 + r;
                    pref[i] = make_uint2(0u, 0u);
                    if (m < N_NODES)
                        pref[i] = __ldg((const uint2*)(srcp + (size_t)m * D +
                                                       koff + c4 * 4));
                }
            }

            #pragma unroll
            for (int ks = 0; ks < 2; ks++) {
                int ka = ks * 16;
                int kw = kc * 32 + ks * 16;
                uint32_t A[2][4];
                #pragma unroll
                for (int mf = 0; mf < 2; mf++) {
                    int r0 = warpM * 32 + mf * 16;
                    uint2 t0 = *(const uint2*)&sA[(r0 + g) * APAD + ka + tig * 4];
                    uint2 t1 = *(const uint2*)&sA[(r0 + g + 8) * APAD + ka + tig * 4];
                    A[mf][0] = t0.x; A[mf][1] = t1.x; A[mf][2] = t0.y; A[mf][3] = t1.y;
                }
                #pragma unroll
                for (int nf = 0; nf < 8; nf++) {
                    int nr = warpN * 64 + nf * 8 + g;
                    uint2 b = *(const uint2*)&sW[nr * KPAD + kw + tig * 4];
                    #pragma unroll
                    for (int mf = 0; mf < 2; mf++)
                        mma_f16(acc[mf][nf], A[mf][0], A[mf][1], A[mf][2], A[mf][3],
                                b.x, b.y);
                }
            }
        }

        // epilogue: + bias, relu; fp16 store (hidden layers) or fp32 (last)
        #pragma unroll
        for (int mf = 0; mf < 2; mf++) {
            #pragma unroll
            for (int nf = 0; nf < 8; nf++) {
                int row0 = m0 + warpM * 32 + mf * 16 + g;
                int col = warpN * 64 + nf * 8 + tig * 2;
                float r0 = acc[mf][nf][0] + bx[nf]; r0 = r0 > 0.f ? r0 : 0.f;
                float r1 = acc[mf][nf][1] + by[nf]; r1 = r1 > 0.f ? r1 : 0.f;
                float r2 = acc[mf][nf][2] + bx[nf]; r2 = r2 > 0.f ? r2 : 0.f;
                float r3 = acc[mf][nf][3] + by[nf]; r3 = r3 > 0.f ? r3 : 0.f;
                if (row0 < N_NODES) {
                    if (out32) *(float2*)&out32[(size_t)row0 * D + col] =
                        make_float2(r0, r1);
                    if (out16) *(__half2*)&out16[(size_t)row0 * D + col] =
                        __floats2half2_rn(r0, r1);
                }
                if (row0 + 8 < N_NODES) {
                    if (out32) *(float2*)&out32[(size_t)(row0 + 8) * D + col] =
                        make_float2(r2, r3);
                    if (out16) *(__half2*)&out16[(size_t)(row0 + 8) * D + col] =
                        __floats2half2_rn(r2, r3);
                }
            }
        }
        __syncthreads();   // A buffers reused next tile
    }
}

// ---------------- launch ----------------
extern "C" void kernel_launch(void* const* d_in, const int* in_sizes, int n_in,
                              void* d_out, int out_size)
{
    const float* x       = (const float*)d_in[0];
    const float* W_self  = (const float*)d_in[1];
    const float* W_neigh = (const float*)d_in[2];
    const float* bias    = (const float*)d_in[3];
    const int*   src     = (const int*)d_in[4];
    const int*   dst     = (const int*)d_in[5];
    float* out = (float*)d_out;

    void *px16, *pa16, *pb16, *pn16, *pw;
    cudaGetSymbolAddress(&px16, g_xf16);
    cudaGetSymbolAddress(&pa16, g_hf16a);
    cudaGetSymbolAddress(&pb16, g_hf16b);
    cudaGetSymbolAddress(&pn16, g_hn16);
    cudaGetSymbolAddress(&pw, g_wt16);
    __half* x16 = (__half*)px16;
    __half* a16 = (__half*)pa16;
    __half* b16 = (__half*)pb16;
    __half* hn16 = (__half*)pn16;
    const __half* wt16 = (const __half*)pw;

    static cudaStream_t s2 = nullptr;
    static cudaEvent_t evFork, evPrep;
    if (s2 == nullptr) {
        cudaStreamCreateWithFlags(&s2, cudaStreamNonBlocking);
        cudaEventCreateWithFlags(&evFork, cudaEventDisableTiming);
        cudaEventCreateWithFlags(&evPrep, cudaEventDisableTiming);
        cudaFuncSetAttribute(sage_gemm_kernel,
                             cudaFuncAttributeMaxDynamicSharedMemorySize,
                             GEMM_SMEM_BYTES);
    }

    // fork: convert x -> fp16 and prep all weights, concurrent with CSR build
    cudaEventRecord(evFork, 0);
    cudaStreamWaitEvent(s2, evFork, 0);
    convert_x_kernel<<<(N_NODES * D / 4 + 255) / 256, 256, 0, s2>>>(x);
    prep_w_kernel<<<(3 * 128 * 256 + 255) / 256, 256, 0, s2>>>(W_self, W_neigh);
    cudaEventRecord(evPrep, s2);

    zero_deg_kernel<<<(N_NODES + 255) / 256, 256>>>();
    count_deg_kernel<<<(N_EDGES + 255) / 256, 256>>>(dst);
    scan_offsets_kernel<<<1, 1024>>>();
    fill_csr_kernel<<<(N_EDGES + 255) / 256, 256>>>(src, dst);
    cudaStreamWaitEvent(0, evPrep, 0);    // join: agg needs x16, gemm needs W

    const __half* hin16 = x16;
    __half* houts16[3] = {a16, b16, nullptr};
    float* houts32[3] = {nullptr, nullptr, out};
    for (int l = 0; l < L_LAYERS; l++) {
        aggregate_f16_kernel<<<(N_NODES + 7) / 8, 256>>>(hin16);
        sage_gemm_kernel<<<GEMM_GRID, 256, GEMM_SMEM_BYTES>>>(
            hin16, hn16, wt16 + (size_t)l * 128 * KPAD,
            bias + (size_t)l * D, houts32[l], houts16[l]);
        hin16 = houts16[l];
    }
}